// round 15
// baseline (speedup 1.0000x reference)
#include <cuda_runtime.h>
#include <cuda_bf16.h>
#include <cstdint>

// Problem constants (fixed by the dataset): B=2, N=250000, C=32, S=128
#define NPTS   250000
#define NBATCH 2
#define MTOT   (NPTS * NBATCH)        // 500000
#define CDIM   32
#define SDIM   128
#define GRID_CELLS (NBATCH * SDIM * SDIM * SDIM)  // 4,194,304

#define CHUNK    4096                 // output points per rulebook chunk
#define CHUNKS   ((MTOT + CHUNK - 1) / CHUNK)     // 123
#define SEG      1024                 // pairs per gemm block
#define SEGS     (CHUNK / SEG)        // 4
#define GTHREADS 128                  // gemm block: 4 warps
#define GWARPS   (GTHREADS / 32)
#define FSTRIDE  36                   // tile row stride in words

// Scratch (no cudaMalloc allowed)
__device__ int   g_grid[GRID_CELLS];
__device__ int   g_cnt[27 * CHUNKS];              // valid pairs per (k,chunk)
__device__ int2  g_pairs[27 * CHUNKS * CHUNK];    // compacted (in_idx, out_m)
__device__ float g_x1[MTOT * CDIM];
__device__ float g_x2[MTOT * CDIM];

// ---------------------------------------------------------------------------
// helpers
// ---------------------------------------------------------------------------
__device__ __forceinline__ uint32_t f2tf(float f) {
    uint32_t r;
    asm("cvt.rna.tf32.f32 %0, %1;" : "=r"(r) : "f"(f));
    return r;
}
__device__ __forceinline__ void mma_tf32(float* d, const uint32_t* a,
                                         uint32_t b0, uint32_t b1) {
    asm volatile(
        "mma.sync.aligned.m16n8k8.row.col.f32.tf32.tf32.f32 "
        "{%0,%1,%2,%3}, {%4,%5,%6,%7}, {%8,%9}, {%0,%1,%2,%3};"
        : "+f"(d[0]), "+f"(d[1]), "+f"(d[2]), "+f"(d[3])
        : "r"(a[0]), "r"(a[1]), "r"(a[2]), "r"(a[3]), "r"(b0), "r"(b1));
}
__device__ __forceinline__ void red_add_v2(float* p, float a, float b) {
    asm volatile("red.global.add.v2.f32 [%0], {%1, %2};"
                 :: "l"(p), "f"(a), "f"(b) : "memory");
}
__device__ __forceinline__ uint32_t smem_u32(const void* p) {
    uint32_t a;
    asm("{ .reg .u64 t; cvta.to.shared.u64 t, %1; cvt.u32.u64 %0, t; }"
        : "=r"(a) : "l"(p));
    return a;
}
__device__ __forceinline__ void cp_async16(uint32_t dst, const void* src) {
    asm volatile("cp.async.cg.shared.global [%0], [%1], 16;"
                 :: "r"(dst), "l"(src) : "memory");
}
__device__ __forceinline__ void cp_commit() {
    asm volatile("cp.async.commit_group;" ::: "memory");
}
__device__ __forceinline__ void cp_wait0() {
    asm volatile("cp.async.wait_group 0;" ::: "memory");
}

// ---------------------------------------------------------------------------
// fused prepass: grid init to -1 + zero all three accumulation buffers
// ---------------------------------------------------------------------------
__global__ void init_zero_kernel(float* __restrict__ a,
                                 float* __restrict__ b,
                                 float* __restrict__ c) {
    int i = blockIdx.x * blockDim.x + threadIdx.x;
    if (i < GRID_CELLS / 4)
        reinterpret_cast<int4*>(g_grid)[i] = make_int4(-1, -1, -1, -1);
    const int n4 = MTOT * CDIM / 4;
    const float4 z = make_float4(0.f, 0.f, 0.f, 0.f);
    if (i < n4) {
        reinterpret_cast<float4*>(a)[i] = z;
        reinterpret_cast<float4*>(b)[i] = z;
        reinterpret_cast<float4*>(c)[i] = z;
    }
}

// ---------------------------------------------------------------------------
// scatter point index into grid
// ---------------------------------------------------------------------------
__global__ void scatter_kernel(const int* __restrict__ coords) {
    int m = blockIdx.x * blockDim.x + threadIdx.x;
    if (m >= MTOT) return;
    int b = (m >= NPTS) ? 1 : 0;
    int x = coords[3 * m + 0];
    int y = coords[3 * m + 1];
    int z = coords[3 * m + 2];
    g_grid[((b * SDIM + x) * SDIM + y) * SDIM + z] = m;
}

// ---------------------------------------------------------------------------
// build compacted rulebook
// ---------------------------------------------------------------------------
__global__ void build_rules_kernel(const int* __restrict__ coords) {
    __shared__ int s_cnt;
    const int tid  = threadIdx.x;
    const int lane = tid & 31;
    const int k    = blockIdx.y;
    const int base = blockIdx.x * CHUNK;

    if (tid == 0) s_cnt = 0;
    __syncthreads();

    const int dx = k / 9 - 1;
    const int dy = (k / 3) % 3 - 1;
    const int dz = k % 3 - 1;
    int2* pout = g_pairs + ((long long)k * CHUNKS + blockIdx.x) * CHUNK;

    #pragma unroll
    for (int it = 0; it < CHUNK / 256; ++it) {
        const int m = base + it * 256 + tid;
        int idx = -1;
        if (m < MTOT) {
            const int b  = (m >= NPTS) ? 1 : 0;
            const int nx = coords[3 * m + 0] + dx;
            const int ny = coords[3 * m + 1] + dy;
            const int nz = coords[3 * m + 2] + dz;
            if ((unsigned)nx < SDIM && (unsigned)ny < SDIM && (unsigned)nz < SDIM)
                idx = __ldg(g_grid + ((b * SDIM + nx) * SDIM + ny) * SDIM + nz);
        }
        unsigned bal = __ballot_sync(0xffffffffu, idx >= 0);
        int cnt = __popc(bal);
        int bpos = 0;
        if (lane == 0 && cnt) bpos = atomicAdd(&s_cnt, cnt);
        bpos = __shfl_sync(0xffffffffu, bpos, 0);
        if (idx >= 0) {
            int r = __popc(bal & ((1u << lane) - 1));
            pout[bpos + r] = make_int2(idx, m);
        }
    }
    __syncthreads();
    if (tid == 0) g_cnt[k * CHUNKS + blockIdx.x] = s_cnt;
}

// ---------------------------------------------------------------------------
// gather-GEMM-scatter on tensor cores (tf32 mma.sync, 2-term split),
// M=32 per warp: two m16 row-tiles share each B fragment.
// grid: (CHUNKS*SEGS, 27). Block 128 = 4 warps; warp-iter = 32 pairs x 32
// couts, K=32 as 4 k-steps.  D = Ah*Bh + Al*Bh + Ah*Bl (fp32-grade).
// W fragments pre-packed {bh0,bh1,bl0,bl1} as uint4 -> one LDS.128 per
// (kk,nn), reused by both tiles.  Gather: row=lane, 8 cp.async.cg 16B,
// double-buffered.  Scatter: red.global.add.v2.f32 from D fragments.
// ---------------------------------------------------------------------------
__global__ __launch_bounds__(GTHREADS, 5)
void spconv_gemm_kernel(const float* __restrict__ in,
                        float*       __restrict__ out,
                        const float* __restrict__ W,
                        int relu_in)
{
    __shared__ __align__(16) uint4 s_B[512];                        // 8 KB
    __shared__ __align__(16) float s_F[GWARPS][2][32 * FSTRIDE];    // 36.9 KB

    const int k    = blockIdx.y;
    const int c    = blockIdx.x / SEGS;
    const int seg  = blockIdx.x - c * SEGS;
    const int V    = __ldg(g_cnt + k * CHUNKS + c);
    const int lo   = seg * SEG;
    if (lo >= V) return;                         // uniform
    const int hi   = min(V, lo + SEG);

    const int tid  = threadIdx.x;
    const int lane = tid & 31;
    const int wid  = tid >> 5;

    // pack W fragments: s_B[(kk*4+nn)*32 + l] = {bh0,bh1,bl0,bl1}
    // reg0: W[kk*8 + t][8nn+g], reg1: W[kk*8 + t + 4][8nn+g]
    const float* Wk = W + k * (CDIM * CDIM);
    for (int i = tid; i < 512; i += GTHREADS) {
        const int l  = i & 31;
        const int nn = (i >> 5) & 3;
        const int kk = i >> 7;
        const int g  = l >> 2;
        const int t  = l & 3;
        const float w0 = __ldg(Wk + (kk * 8 + t    ) * CDIM + 8 * nn + g);
        const float w1 = __ldg(Wk + (kk * 8 + t + 4) * CDIM + 8 * nn + g);
        const uint32_t h0 = f2tf(w0), h1 = f2tf(w1);
        s_B[i] = make_uint4(h0, h1,
                            f2tf(w0 - __uint_as_float(h0)),
                            f2tf(w1 - __uint_as_float(h1)));
    }
    __syncthreads();

    const int2* pairs = g_pairs + ((long long)k * CHUNKS + c) * CHUNK;
    const int g_ = lane >> 2;                    // groupID 0..7
    const int t_ = lane & 3;                     // thread-in-group 0..3

    int g0 = lo + wid * 32;
    if (g0 >= hi) return;

    const uint32_t tb[2] = { smem_u32(s_F[wid][0]), smem_u32(s_F[wid][1]) };

    // gather one 32-row tile: lane = row, 8x 16B cp.async
    auto issue_gather = [&](uint32_t tbase, int2 prx) {
        const float* sp = in + (long long)prx.x * CDIM;
        const uint32_t dbase = tbase + lane * (FSTRIDE * 4);
        #pragma unroll
        for (int j = 0; j < 8; j++)
            cp_async16(dbase + 16 * j, sp + 4 * j);
        cp_commit();
    };

    // prologue (lane holds the pair of row = lane)
    int2 pr_cur = (g0 + lane < hi) ? __ldg(pairs + g0 + lane) : make_int2(0, 0);
    issue_gather(tb[0], pr_cur);
    int2 pr_nxt = (g0 + 128 + lane < hi) ? __ldg(pairs + g0 + 128 + lane)
                                         : make_int2(0, 0);
    cp_wait0();
    __syncwarp();

    int buf = 0;
    for (; g0 < hi; g0 += GWARPS * 32) {
        const bool more = (g0 + 128 < hi);
        if (more) issue_gather(tb[buf ^ 1], pr_nxt);
        int2 pr_n2 = (g0 + 256 + lane < hi) ? __ldg(pairs + g0 + 256 + lane)
                                            : make_int2(0, 0);

        const float* tf = s_F[wid][buf];
        float acc0[4][4], acc1[4][4];
        #pragma unroll
        for (int nn = 0; nn < 4; nn++)
            #pragma unroll
            for (int i = 0; i < 4; i++) { acc0[nn][i] = 0.f; acc1[nn][i] = 0.f; }

        #pragma unroll
        for (int kk = 0; kk < 4; kk++) {
            // A fragments for both m16 tiles
            float a0[4], a1[4];
            a0[0] = tf[(g_     ) * FSTRIDE + kk * 8 + t_];
            a0[1] = tf[(g_ +  8) * FSTRIDE + kk * 8 + t_];
            a0[2] = tf[(g_     ) * FSTRIDE + kk * 8 + t_ + 4];
            a0[3] = tf[(g_ +  8) * FSTRIDE + kk * 8 + t_ + 4];
            a1[0] = tf[(g_ + 16) * FSTRIDE + kk * 8 + t_];
            a1[1] = tf[(g_ + 24) * FSTRIDE + kk * 8 + t_];
            a1[2] = tf[(g_ + 16) * FSTRIDE + kk * 8 + t_ + 4];
            a1[3] = tf[(g_ + 24) * FSTRIDE + kk * 8 + t_ + 4];
            if (relu_in) {
                #pragma unroll
                for (int i = 0; i < 4; i++) {
                    a0[i] = fmaxf(a0[i], 0.f);
                    a1[i] = fmaxf(a1[i], 0.f);
                }
            }
            uint32_t ah0[4], al0[4], ah1[4], al1[4];
            #pragma unroll
            for (int i = 0; i < 4; i++) {
                ah0[i] = f2tf(a0[i]);
                al0[i] = f2tf(a0[i] - __uint_as_float(ah0[i]));
                ah1[i] = f2tf(a1[i]);
                al1[i] = f2tf(a1[i] - __uint_as_float(ah1[i]));
            }
            #pragma unroll
            for (int nn = 0; nn < 4; nn++) {
                const uint4 b = s_B[(kk * 4 + nn) * 32 + lane];
                mma_tf32(acc0[nn], ah0, b.x, b.y);
                mma_tf32(acc0[nn], al0, b.x, b.y);
                mma_tf32(acc0[nn], ah0, b.z, b.w);
                mma_tf32(acc1[nn], ah1, b.x, b.y);
                mma_tf32(acc1[nn], al1, b.x, b.y);
                mma_tf32(acc1[nn], ah1, b.z, b.w);
            }
        }

        // scatter from D fragments: tile0 rows g_, g_+8; tile1 +16, +24
        const int moA = __shfl_sync(0xffffffffu, pr_cur.y, g_);
        const int moB = __shfl_sync(0xffffffffu, pr_cur.y, g_ + 8);
        const int moC = __shfl_sync(0xffffffffu, pr_cur.y, g_ + 16);
        const int moD = __shfl_sync(0xffffffffu, pr_cur.y, g_ + 24);
        const bool vA = (g0 + g_      < hi);
        const bool vB = (g0 + g_ +  8 < hi);
        const bool vC = (g0 + g_ + 16 < hi);
        const bool vD = (g0 + g_ + 24 < hi);
        #pragma unroll
        for (int nn = 0; nn < 4; nn++) {
            const int co = nn * 8 + 2 * t_;
            if (vA) red_add_v2(out + (long long)moA * CDIM + co,
                               acc0[nn][0], acc0[nn][1]);
            if (vB) red_add_v2(out + (long long)moB * CDIM + co,
                               acc0[nn][2], acc0[nn][3]);
            if (vC) red_add_v2(out + (long long)moC * CDIM + co,
                               acc1[nn][0], acc1[nn][1]);
            if (vD) red_add_v2(out + (long long)moD * CDIM + co,
                               acc1[nn][2], acc1[nn][3]);
        }

        if (more) cp_wait0();
        __syncwarp();
        pr_cur = pr_nxt;
        pr_nxt = pr_n2;
        buf ^= 1;
    }
}

// ---------------------------------------------------------------------------
// launch.  init_zero(1), scatter(2), build_rules(3), gemm x3 (4-6).
// ---------------------------------------------------------------------------
extern "C" void kernel_launch(void* const* d_in, const int* in_sizes, int n_in,
                              void* d_out, int out_size)
{
    const float* features = nullptr;
    const int*   coords   = nullptr;
    const float* Ws[3]    = {nullptr, nullptr, nullptr};
    int wcount = 0;

    for (int i = 0; i < n_in; ++i) {
        if (in_sizes[i] == MTOT * CDIM && features == nullptr) {
            features = (const float*)d_in[i];
        } else if (in_sizes[i] == MTOT * 3 && coords == nullptr) {
            coords = (const int*)d_in[i];
        } else if (in_sizes[i] == 27 * CDIM * CDIM && wcount < 3) {
            Ws[wcount++] = (const float*)d_in[i];
        }
    }

    float* x1 = nullptr;
    float* x2 = nullptr;
    cudaGetSymbolAddress((void**)&x1, g_x1);
    cudaGetSymbolAddress((void**)&x2, g_x2);
    float* out = (float*)d_out;

    cudaFuncSetAttribute(spconv_gemm_kernel,
                         cudaFuncAttributePreferredSharedMemoryCarveout, 100);

    // 1) fused grid-init + zero of all accumulation buffers
    {
        const int n = MTOT * CDIM / 4;
        init_zero_kernel<<<(n + 255) / 256, 256>>>(x1, x2, out);
    }
    // 2) scatter
    scatter_kernel<<<(MTOT + 255) / 256, 256>>>(coords);
    // 3) compacted rulebook (shared by all 3 layers)
    {
        dim3 g(CHUNKS, 27);
        build_rules_kernel<<<g, 256>>>(coords);
    }
    // 4-6) three layers of gather-GEMM-scatter (segmented grid)
    {
        dim3 g(CHUNKS * SEGS, 27);
        spconv_gemm_kernel<<<g, GTHREADS>>>(features, x1, Ws[0], 0);
        spconv_gemm_kernel<<<g, GTHREADS>>>(x1,       x2, Ws[1], 1);
        spconv_gemm_kernel<<<g, GTHREADS>>>(x2,      out, Ws[2], 1);
    }
}

// round 17
// speedup vs baseline: 1.4170x; 1.4170x over previous
#include <cuda_runtime.h>
#include <cuda_bf16.h>
#include <cstdint>

// Problem constants (fixed by the dataset): B=2, N=250000, C=32, S=128
#define NPTS   250000
#define NBATCH 2
#define MTOT   (NPTS * NBATCH)        // 500000
#define CDIM   32
#define SDIM   128
#define GRID_CELLS (NBATCH * SDIM * SDIM * SDIM)  // 4,194,304

#define CHUNK    4096                 // output points per rulebook chunk
#define CHUNKS   ((MTOT + CHUNK - 1) / CHUNK)     // 123
#define SEG      1024                 // pairs per gemm block
#define SEGS     (CHUNK / SEG)        // 4
#define GTHREADS 128                  // gemm block: 4 warps
#define GWARPS   (GTHREADS / 32)
#define FSTRIDE  36                   // tile row stride in words

// Scratch (no cudaMalloc allowed)
__device__ int   g_grid[GRID_CELLS];
__device__ int   g_cnt[27 * CHUNKS];              // valid pairs per (k,chunk)
__device__ int2  g_pairs[27 * CHUNKS * CHUNK];    // compacted (in_idx, out_m)
__device__ float g_x1[MTOT * CDIM];
__device__ float g_x2[MTOT * CDIM];

// ---------------------------------------------------------------------------
// helpers
// ---------------------------------------------------------------------------
__device__ __forceinline__ uint32_t f2tf(float f) {
    uint32_t r;
    asm("cvt.rna.tf32.f32 %0, %1;" : "=r"(r) : "f"(f));
    return r;
}
__device__ __forceinline__ void mma_tf32(float* d, const uint32_t* a,
                                         uint32_t b0, uint32_t b1) {
    asm volatile(
        "mma.sync.aligned.m16n8k8.row.col.f32.tf32.tf32.f32 "
        "{%0,%1,%2,%3}, {%4,%5,%6,%7}, {%8,%9}, {%0,%1,%2,%3};"
        : "+f"(d[0]), "+f"(d[1]), "+f"(d[2]), "+f"(d[3])
        : "r"(a[0]), "r"(a[1]), "r"(a[2]), "r"(a[3]), "r"(b0), "r"(b1));
}
__device__ __forceinline__ void red_add_v2(float* p, float a, float b) {
    asm volatile("red.global.add.v2.f32 [%0], {%1, %2};"
                 :: "l"(p), "f"(a), "f"(b) : "memory");
}
__device__ __forceinline__ uint32_t smem_u32(const void* p) {
    uint32_t a;
    asm("{ .reg .u64 t; cvta.to.shared.u64 t, %1; cvt.u32.u64 %0, t; }"
        : "=r"(a) : "l"(p));
    return a;
}
__device__ __forceinline__ void cp_async16(uint32_t dst, const void* src) {
    asm volatile("cp.async.cg.shared.global [%0], [%1], 16;"
                 :: "r"(dst), "l"(src) : "memory");
}
__device__ __forceinline__ void cp_commit() {
    asm volatile("cp.async.commit_group;" ::: "memory");
}
__device__ __forceinline__ void cp_wait0() {
    asm volatile("cp.async.wait_group 0;" ::: "memory");
}

// ---------------------------------------------------------------------------
// fused prepass: grid init to -1 + zero all three accumulation buffers
// ---------------------------------------------------------------------------
__global__ void init_zero_kernel(float* __restrict__ a,
                                 float* __restrict__ b,
                                 float* __restrict__ c) {
    int i = blockIdx.x * blockDim.x + threadIdx.x;
    if (i < GRID_CELLS / 4)
        reinterpret_cast<int4*>(g_grid)[i] = make_int4(-1, -1, -1, -1);
    const int n4 = MTOT * CDIM / 4;
    const float4 z = make_float4(0.f, 0.f, 0.f, 0.f);
    if (i < n4) {
        reinterpret_cast<float4*>(a)[i] = z;
        reinterpret_cast<float4*>(b)[i] = z;
        reinterpret_cast<float4*>(c)[i] = z;
    }
}

// ---------------------------------------------------------------------------
// scatter point index into grid
// ---------------------------------------------------------------------------
__global__ void scatter_kernel(const int* __restrict__ coords) {
    int m = blockIdx.x * blockDim.x + threadIdx.x;
    if (m >= MTOT) return;
    int b = (m >= NPTS) ? 1 : 0;
    int x = coords[3 * m + 0];
    int y = coords[3 * m + 1];
    int z = coords[3 * m + 2];
    g_grid[((b * SDIM + x) * SDIM + y) * SDIM + z] = m;
}

// ---------------------------------------------------------------------------
// build compacted rulebook
// ---------------------------------------------------------------------------
__global__ void build_rules_kernel(const int* __restrict__ coords) {
    __shared__ int s_cnt;
    const int tid  = threadIdx.x;
    const int lane = tid & 31;
    const int k    = blockIdx.y;
    const int base = blockIdx.x * CHUNK;

    if (tid == 0) s_cnt = 0;
    __syncthreads();

    const int dx = k / 9 - 1;
    const int dy = (k / 3) % 3 - 1;
    const int dz = k % 3 - 1;
    int2* pout = g_pairs + ((long long)k * CHUNKS + blockIdx.x) * CHUNK;

    #pragma unroll
    for (int it = 0; it < CHUNK / 256; ++it) {
        const int m = base + it * 256 + tid;
        int idx = -1;
        if (m < MTOT) {
            const int b  = (m >= NPTS) ? 1 : 0;
            const int nx = coords[3 * m + 0] + dx;
            const int ny = coords[3 * m + 1] + dy;
            const int nz = coords[3 * m + 2] + dz;
            if ((unsigned)nx < SDIM && (unsigned)ny < SDIM && (unsigned)nz < SDIM)
                idx = __ldg(g_grid + ((b * SDIM + nx) * SDIM + ny) * SDIM + nz);
        }
        unsigned bal = __ballot_sync(0xffffffffu, idx >= 0);
        int cnt = __popc(bal);
        int bpos = 0;
        if (lane == 0 && cnt) bpos = atomicAdd(&s_cnt, cnt);
        bpos = __shfl_sync(0xffffffffu, bpos, 0);
        if (idx >= 0) {
            int r = __popc(bal & ((1u << lane) - 1));
            pout[bpos + r] = make_int2(idx, m);
        }
    }
    __syncthreads();
    if (tid == 0) g_cnt[k * CHUNKS + blockIdx.x] = s_cnt;
}

// ---------------------------------------------------------------------------
// gather-GEMM-scatter on tensor cores (tf32 mma.sync, 2-term split).
// R14 structure (m16 warp tiles, 64 pairs/block-iter, cp.async double
// buffer) + packed B fragments: {bh0,bh1,bl0,bl1} as one uint4 ->
// 16 LDS.128 per iteration instead of 64 LDS.32.
//   D = Ah*Bh + Al*Bh + Ah*Bl   (fp32-grade, Al*Bl dropped)
// Scatter from D fragments via red.global.add.v2.f32.
// ---------------------------------------------------------------------------
__global__ __launch_bounds__(GTHREADS, 7)
void spconv_gemm_kernel(const float* __restrict__ in,
                        float*       __restrict__ out,
                        const float* __restrict__ W,
                        int relu_in)
{
    __shared__ __align__(16) uint4 s_B[512];                        // 8 KB
    __shared__ __align__(16) float s_F[GWARPS][2][16 * FSTRIDE];    // 18 KB

    const int k    = blockIdx.y;
    const int c    = blockIdx.x / SEGS;
    const int seg  = blockIdx.x - c * SEGS;
    const int V    = __ldg(g_cnt + k * CHUNKS + c);
    const int lo   = seg * SEG;
    if (lo >= V) return;                         // uniform
    const int hi   = min(V, lo + SEG);

    const int tid  = threadIdx.x;
    const int lane = tid & 31;
    const int wid  = tid >> 5;

    // pack W fragments: s_B[(kk*4+nn)*32 + l] = {bh0,bh1,bl0,bl1}
    // reg0: W[kk*8 + t][8nn+g], reg1: W[kk*8 + t + 4][8nn+g]
    const float* Wk = W + k * (CDIM * CDIM);
    for (int i = tid; i < 512; i += GTHREADS) {
        const int l  = i & 31;
        const int nn = (i >> 5) & 3;
        const int kk = i >> 7;
        const int g  = l >> 2;
        const int t  = l & 3;
        const float w0 = __ldg(Wk + (kk * 8 + t) * CDIM + 8 * nn + g);
        const float w1 = __ldg(Wk + (kk * 8 + t + 4) * CDIM + 8 * nn + g);
        const uint32_t h0 = f2tf(w0);
        const uint32_t h1 = f2tf(w1);
        const uint32_t l0 = f2tf(w0 - __uint_as_float(h0));
        const uint32_t l1 = f2tf(w1 - __uint_as_float(h1));
        uint4 pk;
        pk.x = h0; pk.y = h1; pk.z = l0; pk.w = l1;
        s_B[i] = pk;
    }
    __syncthreads();

    const int2* pairs = g_pairs + ((long long)k * CHUNKS + c) * CHUNK;
    const int g_ = lane >> 2;                    // groupID 0..7
    const int t_ = lane & 3;                     // thread-in-group 0..3
    const int grow = lane & 15;                  // gather row 0..15
    const int ghalf = lane >> 4;                 // gather half 0..1

    int g0 = lo + wid * 16;
    if (g0 >= hi) return;

    const uint32_t tb[2] = { smem_u32(s_F[wid][0]), smem_u32(s_F[wid][1]) };

    // gather one 16-row tile: lane covers row (lane&15), 64B half (lane>>4)
    auto issue_gather = [&](uint32_t tbase, int2 prx) {
        const float* sp = in + (long long)prx.x * CDIM + ghalf * 16;
        const uint32_t dbase = tbase + (grow * FSTRIDE + ghalf * 16) * 4;
        #pragma unroll
        for (int j = 0; j < 4; j++)
            cp_async16(dbase + 16 * j, sp + 4 * j);
        cp_commit();
    };

    // prologue (each lane holds the pair of row lane&15)
    int2 pr_cur = (g0 + grow < hi) ? __ldg(pairs + g0 + grow) : make_int2(0, 0);
    issue_gather(tb[0], pr_cur);
    int2 pr_nxt = (g0 + 64 + grow < hi) ? __ldg(pairs + g0 + 64 + grow)
                                        : make_int2(0, 0);
    cp_wait0();
    __syncwarp();

    int buf = 0;
    for (; g0 < hi; g0 += GWARPS * 16) {
        const bool more = (g0 + 64 < hi);
        if (more) issue_gather(tb[buf ^ 1], pr_nxt);
        int2 pr_n2 = (g0 + 128 + grow < hi) ? __ldg(pairs + g0 + 128 + grow)
                                            : make_int2(0, 0);

        const float* tf = s_F[wid][buf];
        float acc[4][4];
        #pragma unroll
        for (int nn = 0; nn < 4; nn++)
            #pragma unroll
            for (int i = 0; i < 4; i++) acc[nn][i] = 0.f;

        #pragma unroll
        for (int kk = 0; kk < 4; kk++) {
            // A fragment (m16 x k8), rows g_, g_+8; cols kk*8 + t_, +4
            float a[4];
            a[0] = tf[(g_    ) * FSTRIDE + kk * 8 + t_];
            a[1] = tf[(g_ + 8) * FSTRIDE + kk * 8 + t_];
            a[2] = tf[(g_    ) * FSTRIDE + kk * 8 + t_ + 4];
            a[3] = tf[(g_ + 8) * FSTRIDE + kk * 8 + t_ + 4];
            if (relu_in) {
                #pragma unroll
                for (int i = 0; i < 4; i++) a[i] = fmaxf(a[i], 0.f);
            }
            uint32_t ah[4], al[4];
            #pragma unroll
            for (int i = 0; i < 4; i++) {
                ah[i] = f2tf(a[i]);
                al[i] = f2tf(a[i] - __uint_as_float(ah[i]));
            }
            #pragma unroll
            for (int nn = 0; nn < 4; nn++) {
                const uint4 b = s_B[(kk * 4 + nn) * 32 + lane];
                mma_tf32(acc[nn], ah, b.x, b.y);
                mma_tf32(acc[nn], al, b.x, b.y);
                mma_tf32(acc[nn], ah, b.z, b.w);
            }
        }

        // scatter from D fragments: rows g_ (c0,c1) and g_+8 (c2,c3)
        const int moA = __shfl_sync(0xffffffffu, pr_cur.y, g_);
        const int moB = __shfl_sync(0xffffffffu, pr_cur.y, g_ + 8);
        const bool vA = (g0 + g_ < hi);
        const bool vB = (g0 + g_ + 8 < hi);
        #pragma unroll
        for (int nn = 0; nn < 4; nn++) {
            if (vA) red_add_v2(out + (long long)moA * CDIM + nn * 8 + 2 * t_,
                               acc[nn][0], acc[nn][1]);
            if (vB) red_add_v2(out + (long long)moB * CDIM + nn * 8 + 2 * t_,
                               acc[nn][2], acc[nn][3]);
        }

        if (more) cp_wait0();
        __syncwarp();
        pr_cur = pr_nxt;
        pr_nxt = pr_n2;
        buf ^= 1;
    }
}

// ---------------------------------------------------------------------------
// launch.  init_zero(1), scatter(2), build_rules(3), gemm x3 (4-6).
// ---------------------------------------------------------------------------
extern "C" void kernel_launch(void* const* d_in, const int* in_sizes, int n_in,
                              void* d_out, int out_size)
{
    const float* features = nullptr;
    const int*   coords   = nullptr;
    const float* Ws[3]    = {nullptr, nullptr, nullptr};
    int wcount = 0;

    for (int i = 0; i < n_in; ++i) {
        if (in_sizes[i] == MTOT * CDIM && features == nullptr) {
            features = (const float*)d_in[i];
        } else if (in_sizes[i] == MTOT * 3 && coords == nullptr) {
            coords = (const int*)d_in[i];
        } else if (in_sizes[i] == 27 * CDIM * CDIM && wcount < 3) {
            Ws[wcount++] = (const float*)d_in[i];
        }
    }

    float* x1 = nullptr;
    float* x2 = nullptr;
    cudaGetSymbolAddress((void**)&x1, g_x1);
    cudaGetSymbolAddress((void**)&x2, g_x2);
    float* out = (float*)d_out;

    cudaFuncSetAttribute(spconv_gemm_kernel,
                         cudaFuncAttributePreferredSharedMemoryCarveout, 100);

    // 1) fused grid-init + zero of all accumulation buffers
    {
        const int n = MTOT * CDIM / 4;
        init_zero_kernel<<<(n + 255) / 256, 256>>>(x1, x2, out);
    }
    // 2) scatter
    scatter_kernel<<<(MTOT + 255) / 256, 256>>>(coords);
    // 3) compacted rulebook (shared by all 3 layers)
    {
        dim3 g(CHUNKS, 27);
        build_rules_kernel<<<g, 256>>>(coords);
    }
    // 4-6) three layers of gather-GEMM-scatter (segmented grid)
    {
        dim3 g(CHUNKS * SEGS, 27);
        spconv_gemm_kernel<<<g, GTHREADS>>>(features, x1, Ws[0], 0);
        spconv_gemm_kernel<<<g, GTHREADS>>>(x1,       x2, Ws[1], 1);
        spconv_gemm_kernel<<<g, GTHREADS>>>(x2,      out, Ws[2], 1);
    }
}